// round 4
// baseline (speedup 1.0000x reference)
#include <cuda_runtime.h>

#define DEV_INLINE __device__ __forceinline__
typedef unsigned long long ull;

constexpr int C  = 8;
constexpr int K  = 64;
constexpr int NN = 2048;

// ---- per-(c,k) repacked blob layout (floats) ----
constexpr int BLOB = 5632;               // 22528 B = 1408 x 16B chunks; /128 thr = 11
constexpr int W1S = 0;                   // [64][20] stride-padded, cols 0..15 valid
constexpr int W1T = 1280;
constexpr int W2S = 2560;                // transposed [i][r], stride 20
constexpr int W2T = 3840;
constexpr int B1S = 5120, B1T = 5184;
constexpr int B2S = 5248, B2T = 5264;    // passive order
constexpr int ANE = 5280;                // [act 16 | pas 16] exp(-s)
constexpr int ANF = 5312;                // [act 16 | pas 16] -t*exp(-s)
constexpr int ASUM = 5344;

__device__ float g_blob[C * K * BLOB];
__device__ float g_Bm[C * NN];
__device__ float g_Sn[C * C];

// ---------- packed f32x2 helpers ----------
DEV_INLINE ull pack2(float lo, float hi) {
    ull r; asm("mov.b64 %0, {%1,%2};" : "=l"(r) : "f"(lo), "f"(hi)); return r;
}
DEV_INLINE void unpack2(ull v, float& lo, float& hi) {
    asm("mov.b64 {%0,%1}, %2;" : "=f"(lo), "=f"(hi) : "l"(v));
}
DEV_INLINE ull ffma2(ull a, ull b, ull c) {
    ull d; asm("fma.rn.f32x2 %0, %1, %2, %3;" : "=l"(d) : "l"(a), "l"(b), "l"(c)); return d;
}
DEV_INLINE ull add2(ull a, ull b) {
    ull d; asm("add.rn.f32x2 %0, %1, %2;" : "=l"(d) : "l"(a), "l"(b)); return d;
}
DEV_INLINE ull mul2(ull a, ull b) {
    ull d; asm("mul.rn.f32x2 %0, %1, %2;" : "=l"(d) : "l"(a), "l"(b)); return d;
}
DEV_INLINE ull neg2(ull a) { return a ^ 0x8000000080000000ULL; }

// ---------- cp.async staging ----------
DEV_INLINE void stage(float* sdst, const float* gsrc, int tid) {
    unsigned sa = (unsigned)__cvta_generic_to_shared(sdst);
    #pragma unroll
    for (int i = 0; i < 11; i++) {
        int ch = tid + i * 128;
        asm volatile("cp.async.cg.shared.global [%0], [%1], 16;"
                     :: "r"(sa + ch * 16), "l"(gsrc + ch * 4));
    }
    asm volatile("cp.async.commit_group;");
}
DEV_INLINE void wait_stage() {
    asm volatile("cp.async.wait_group 0;" ::: "memory");
}

// ---------- repack: gather/compact/transpose weights once ----------
__global__ void __launch_bounds__(128)
repack_kernel(const float* __restrict__ sW1, const float* __restrict__ sb1,
              const float* __restrict__ sW2, const float* __restrict__ sb2,
              const float* __restrict__ tW1, const float* __restrict__ tb1,
              const float* __restrict__ tW2, const float* __restrict__ tb2,
              const float* __restrict__ anS, const float* __restrict__ anT)
{
    const int ck = blockIdx.x;          // c*64+k
    const int k = ck & 63;
    const int A = k & 1, PO = 1 - A;    // active / passive parity
    float* B = g_blob + (size_t)ck * BLOB;
    const int tid = threadIdx.x;
    const size_t wo = (size_t)ck * 2048;

    for (int idx = tid; idx < 1024; idx += 128) {
        int i = idx >> 4, j = idx & 15;
        B[W1S + i * 20 + j] = sW1[wo + i * 32 + 2 * j + A];
        B[W1T + i * 20 + j] = tW1[wo + i * 32 + 2 * j + A];
        B[W2S + i * 20 + j] = sW2[wo + (2 * j + PO) * 64 + i];
        B[W2T + i * 20 + j] = tW2[wo + (2 * j + PO) * 64 + i];
    }
    if (tid < 64) {
        B[B1S + tid] = sb1[ck * 64 + tid];
        B[B1T + tid] = tb1[ck * 64 + tid];
    } else if (tid < 80) {
        int r = tid - 64;
        B[B2S + r] = sb2[ck * 32 + 2 * r + PO];
        B[B2T + r] = tb2[ck * 32 + 2 * r + PO];
    } else if (tid < 112) {
        int q = tid - 80;               // 0..31: [act 16 | pas 16]
        int dim = (q < 16) ? (2 * q + A) : (2 * (q - 16) + PO);
        float a = anS[ck * 32 + dim];
        float t = anT[ck * 32 + dim];
        float e = __expf(-a);
        B[ANE + q] = e;
        B[ANF + q] = -t * e;
    } else if (tid == 112) {
        float s = 0.f;
        for (int d = 0; d < 32; d++) s += anS[ck * 32 + d];
        B[ASUM] = s;
    }
}

// ---------- one inverse layer: quarter-split hidden, 1 node/thread ----------
DEV_INLINE void layer_compute(const float* __restrict__ sb, int q,
                              ull (&a)[8], ull (&p)[8], float& ld)
{
    // ActNorm inverse (E/F stored in act|pas order)
    const ull* E = (const ull*)(sb + ANE);
    const ull* F = (const ull*)(sb + ANF);
    #pragma unroll
    for (int j = 0; j < 8; j++) {
        a[j] = ffma2(a[j], E[j],     F[j]);
        p[j] = ffma2(p[j], E[8 + j], F[8 + j]);
    }
    ld -= sb[ASUM];

    // 16 outputs as 8 packed pairs
    ull s[8], t[8];
    const ull* b2s = (const ull*)(sb + B2S);
    const ull* b2t = (const ull*)(sb + B2T);
    #pragma unroll
    for (int j = 0; j < 8; j++) {
        s[j] = (q == 0) ? b2s[j] : 0ULL;
        t[j] = (q == 0) ? b2t[j] : 0ULL;
    }

    #pragma unroll 4
    for (int il = 0; il < 16; il++) {
        const int gi = il * 4 + q;                // this thread's hidden unit
        const ulonglong2* r1s = (const ulonglong2*)(sb + W1S + gi * 20);
        const ulonglong2* r1t = (const ulonglong2*)(sb + W1T + gi * 20);
        ull as = pack2(sb[B1S + gi], 0.f);
        ull at = pack2(sb[B1T + gi], 0.f);
        #pragma unroll
        for (int ch = 0; ch < 4; ch++) {
            ulonglong2 ws = r1s[ch], wt = r1t[ch];
            as = ffma2(ws.x, a[2 * ch],     as);
            as = ffma2(ws.y, a[2 * ch + 1], as);
            at = ffma2(wt.x, a[2 * ch],     at);
            at = ffma2(wt.y, a[2 * ch + 1], at);
        }
        float x0, x1;
        unpack2(as, x0, x1); float hs = fmaxf(x0 + x1, 0.f);
        unpack2(at, x0, x1); float ht = fmaxf(x0 + x1, 0.f);
        ull hsp = pack2(hs, hs), htp = pack2(ht, ht);

        const ulonglong2* r2s = (const ulonglong2*)(sb + W2S + gi * 20);
        const ulonglong2* r2t = (const ulonglong2*)(sb + W2T + gi * 20);
        #pragma unroll
        for (int ch = 0; ch < 4; ch++) {
            ulonglong2 ws = r2s[ch], wt = r2t[ch];
            s[2 * ch]     = ffma2(ws.x, hsp, s[2 * ch]);
            s[2 * ch + 1] = ffma2(ws.y, hsp, s[2 * ch + 1]);
            t[2 * ch]     = ffma2(wt.x, htp, t[2 * ch]);
            t[2 * ch + 1] = ffma2(wt.y, htp, t[2 * ch + 1]);
        }
    }

    // butterfly over the 4 quarter-threads
    #pragma unroll
    for (int j = 0; j < 8; j++) {
        s[j] = add2(s[j], __shfl_xor_sync(0xffffffffu, s[j], 1));
        s[j] = add2(s[j], __shfl_xor_sync(0xffffffffu, s[j], 2));
        t[j] = add2(t[j], __shfl_xor_sync(0xffffffffu, t[j], 1));
        t[j] = add2(t[j], __shfl_xor_sync(0xffffffffu, t[j], 2));
    }

    // passive update + logdet (redundant across quarters, consistent)
    #pragma unroll
    for (int j = 0; j < 8; j++) {
        float sa, sbv;
        unpack2(s[j], sa, sbv);
        ld -= (sa + sbv);
        ull e2 = pack2(__expf(-sa), __expf(-sbv));
        p[j] = ffma2(p[j], e2, neg2(mul2(t[j], e2)));
    }
}

__global__ void __launch_bounds__(128, 4)
flow_kernel(const float* __restrict__ nodes,
            const float* __restrict__ loc, const float* __restrict__ lsc)
{
    __shared__ __align__(16) float sbuf[2][BLOB];
    const int tid  = threadIdx.x;
    const int q    = tid & 3;            // quarter of hidden units
    const int slot = tid >> 2;           // 0..31
    const int c    = blockIdx.y;
    const int node = blockIdx.x * 32 + slot;

    // z packed by parity: ze[j]=(dims 4j,4j+2), zo[j]=(4j+1,4j+3)
    ull ze[8], zo[8];
    {
        const float4* np = (const float4*)(nodes + (size_t)node * 32);
        #pragma unroll
        for (int j = 0; j < 8; j++) {
            float4 v = np[j];
            ze[j] = pack2(v.x, v.z); zo[j] = pack2(v.y, v.w);
        }
    }
    float ld = 0.f;

    const float* gb = g_blob + (size_t)(c * 64) * BLOB;

    stage(sbuf[0], gb + (size_t)63 * BLOB, tid);
    wait_stage();
    __syncthreads();

    #pragma unroll 1
    for (int k = 63; k > 0; k -= 2) {
        stage(sbuf[1], gb + (size_t)(k - 1) * BLOB, tid);
        // layer k (odd): active = odd dims
        layer_compute(sbuf[0], q, zo, ze, ld);
        wait_stage();
        __syncthreads();
        if (k >= 3) stage(sbuf[0], gb + (size_t)(k - 2) * BLOB, tid);
        // layer k-1 (even): active = even dims
        layer_compute(sbuf[1], q, ze, zo, ld);
        wait_stage();
        __syncthreads();
    }

    // DiagGaussian log_prob
    float acc = 0.f;
    const float* lp = loc + c * 32;
    const float* sp = lsc + c * 32;
    #pragma unroll
    for (int j = 0; j < 8; j++) {
        float e0, e1, o0, o1;
        unpack2(ze[j], e0, e1); unpack2(zo[j], o0, o1);
        float z4[4] = {e0, o0, e1, o1};
        #pragma unroll
        for (int b = 0; b < 4; b++) {
            int d = 4 * j + b;
            float ls = __ldg(sp + d);
            float u  = (z4[b] - __ldg(lp + d)) * __expf(-ls);
            acc += ls + 0.5f * u * u;
        }
    }
    if (q == 0)
        g_Bm[c * NN + node] = __expf(ld - 29.406037829f - acc);
}

// Fold L1 row-normalizers and softmax-normalized S into one 8x8 matrix.
__global__ void norm_kernel(const float* __restrict__ S_unc)
{
    __shared__ float sh_r[8];
    __shared__ float sh_e[64];
    const int tid = threadIdx.x;
    const int w = tid >> 5, lane = tid & 31;

    float s = 0.f;
    for (int i = lane; i < NN; i += 32) s += g_Bm[w * NN + i];
    #pragma unroll
    for (int o = 16; o; o >>= 1) s += __shfl_xor_sync(0xffffffffu, s, o);
    if (lane == 0) sh_r[w] = fmaxf(s, 1e-12f);
    if (tid < 64) sh_e[tid] = expf(S_unc[tid]);
    __syncthreads();
    if (tid < 64) {
        float tot = 0.f;
        #pragma unroll
        for (int i = 0; i < 64; i++) tot += sh_e[i];
        int c1 = tid >> 3, c2 = tid & 7;
        g_Sn[tid] = sh_e[tid] / (tot * sh_r[c1] * sh_r[c2]);
    }
}

__global__ void __launch_bounds__(256)
out_kernel(float* __restrict__ out)
{
    __shared__ float B1[8][64];
    __shared__ float B2[8][64];
    __shared__ float T2[8][64];
    const int tid = threadIdx.x;
    const int n10 = blockIdx.y * 64;
    const int n20 = blockIdx.x * 64;

    for (int t = tid; t < 512; t += 256) {
        int cc = t >> 6, j = t & 63;
        B1[cc][j] = g_Bm[cc * NN + n10 + j];
        B2[cc][j] = g_Bm[cc * NN + n20 + j];
    }
    __syncthreads();
    if (tid < 64) {
        #pragma unroll
        for (int c1 = 0; c1 < 8; c1++) {
            float a = 0.f;
            #pragma unroll
            for (int c2 = 0; c2 < 8; c2++)
                a = fmaf(g_Sn[c1 * 8 + c2], B2[c2][tid], a);
            T2[c1][tid] = a;
        }
    }
    __syncthreads();

    const int ty = tid >> 4, tx = tid & 15;
    float bv[4][8], tv[8][4];
    #pragma unroll
    for (int cc = 0; cc < 8; cc++) {
        #pragma unroll
        for (int p = 0; p < 4; p++) {
            bv[p][cc] = B1[cc][ty * 4 + p];
            tv[cc][p] = T2[cc][tx * 4 + p];
        }
    }
    #pragma unroll
    for (int p = 0; p < 4; p++) {
        float4 o = {0.f, 0.f, 0.f, 0.f};
        #pragma unroll
        for (int cc = 0; cc < 8; cc++) {
            o.x = fmaf(bv[p][cc], tv[cc][0], o.x);
            o.y = fmaf(bv[p][cc], tv[cc][1], o.y);
            o.z = fmaf(bv[p][cc], tv[cc][2], o.z);
            o.w = fmaf(bv[p][cc], tv[cc][3], o.w);
        }
        *((float4*)(out + (size_t)(n10 + ty * 4 + p) * NN + n20 + tx * 4)) = o;
    }
}

extern "C" void kernel_launch(void* const* d_in, const int* in_sizes, int n_in,
                              void* d_out, int out_size)
{
    const float* nodes = (const float*)d_in[0];
    const float* sW1   = (const float*)d_in[1];
    const float* sb1   = (const float*)d_in[2];
    const float* sW2   = (const float*)d_in[3];
    const float* sb2   = (const float*)d_in[4];
    const float* tW1   = (const float*)d_in[5];
    const float* tb1   = (const float*)d_in[6];
    const float* tW2   = (const float*)d_in[7];
    const float* tb2   = (const float*)d_in[8];
    const float* anS   = (const float*)d_in[9];
    const float* anT   = (const float*)d_in[10];
    const float* loc   = (const float*)d_in[11];
    const float* lsc   = (const float*)d_in[12];
    const float* S_unc = (const float*)d_in[13];
    float* out = (float*)d_out;

    repack_kernel<<<C * K, 128>>>(sW1, sb1, sW2, sb2, tW1, tb1, tW2, tb2, anS, anT);
    dim3 fg(NN / 32, C);                 // 64 x 8 = 512 blocks, 4 thr/node
    flow_kernel<<<fg, 128>>>(nodes, loc, lsc);
    norm_kernel<<<1, 256>>>(S_unc);
    dim3 og(NN / 64, NN / 64);
    out_kernel<<<og, 256>>>(out);
}

// round 5
// speedup vs baseline: 1.0006x; 1.0006x over previous
#include <cuda_runtime.h>

#define DEV_INLINE __device__ __forceinline__
typedef unsigned long long ull;

constexpr int C  = 8;
constexpr int K  = 64;
constexpr int NN = 2048;

// ---- per-(c,k) repacked blob layout (floats) ----
constexpr int BLOB = 5632;               // 22528 B = 1408 x 16B chunks; /128 thr = 11
constexpr int W1S = 0;                   // [64][20] stride-padded, cols 0..15 valid
constexpr int W1T = 1280;
constexpr int W2S = 2560;                // transposed [i][r], stride 20
constexpr int W2T = 3840;
constexpr int B1S = 5120, B1T = 5184;
constexpr int B2S = 5248, B2T = 5264;    // passive order
constexpr int ANE = 5280;                // [act 16 | pas 16] exp(-s)
constexpr int ANF = 5312;                // [act 16 | pas 16] -t*exp(-s)
constexpr int ASUM = 5344;

__device__ float g_blob[C * K * BLOB];
__device__ float g_Bm[C * NN];
__device__ float g_Sn[C * C];

// ---------- packed f32x2 helpers ----------
DEV_INLINE ull pack2(float lo, float hi) {
    ull r; asm("mov.b64 %0, {%1,%2};" : "=l"(r) : "f"(lo), "f"(hi)); return r;
}
DEV_INLINE void unpack2(ull v, float& lo, float& hi) {
    asm("mov.b64 {%0,%1}, %2;" : "=f"(lo), "=f"(hi) : "l"(v));
}
DEV_INLINE ull ffma2(ull a, ull b, ull c) {
    ull d; asm("fma.rn.f32x2 %0, %1, %2, %3;" : "=l"(d) : "l"(a), "l"(b), "l"(c)); return d;
}
DEV_INLINE ull add2(ull a, ull b) {
    ull d; asm("add.rn.f32x2 %0, %1, %2;" : "=l"(d) : "l"(a), "l"(b)); return d;
}
DEV_INLINE ull mul2(ull a, ull b) {
    ull d; asm("mul.rn.f32x2 %0, %1, %2;" : "=l"(d) : "l"(a), "l"(b)); return d;
}
DEV_INLINE ull neg2(ull a) { return a ^ 0x8000000080000000ULL; }

// ---------- cp.async staging ----------
DEV_INLINE void stage(float* sdst, const float* gsrc, int tid) {
    unsigned sa = (unsigned)__cvta_generic_to_shared(sdst);
    #pragma unroll
    for (int i = 0; i < 11; i++) {
        int ch = tid + i * 128;
        asm volatile("cp.async.cg.shared.global [%0], [%1], 16;"
                     :: "r"(sa + ch * 16), "l"(gsrc + ch * 4));
    }
    asm volatile("cp.async.commit_group;");
}
DEV_INLINE void wait_stage() {
    asm volatile("cp.async.wait_group 0;" ::: "memory");
}

// ---------- repack: gather/compact/transpose weights once ----------
__global__ void __launch_bounds__(128)
repack_kernel(const float* __restrict__ sW1, const float* __restrict__ sb1,
              const float* __restrict__ sW2, const float* __restrict__ sb2,
              const float* __restrict__ tW1, const float* __restrict__ tb1,
              const float* __restrict__ tW2, const float* __restrict__ tb2,
              const float* __restrict__ anS, const float* __restrict__ anT)
{
    const int ck = blockIdx.x;          // c*64+k
    const int k = ck & 63;
    const int A = k & 1, PO = 1 - A;    // active / passive parity
    float* B = g_blob + (size_t)ck * BLOB;
    const int tid = threadIdx.x;
    const size_t wo = (size_t)ck * 2048;

    for (int idx = tid; idx < 1024; idx += 128) {
        int i = idx >> 4, j = idx & 15;
        B[W1S + i * 20 + j] = sW1[wo + i * 32 + 2 * j + A];
        B[W1T + i * 20 + j] = tW1[wo + i * 32 + 2 * j + A];
        B[W2S + i * 20 + j] = sW2[wo + (2 * j + PO) * 64 + i];
        B[W2T + i * 20 + j] = tW2[wo + (2 * j + PO) * 64 + i];
    }
    if (tid < 64) {
        B[B1S + tid] = sb1[ck * 64 + tid];
        B[B1T + tid] = tb1[ck * 64 + tid];
    } else if (tid < 80) {
        int r = tid - 64;
        B[B2S + r] = sb2[ck * 32 + 2 * r + PO];
        B[B2T + r] = tb2[ck * 32 + 2 * r + PO];
    } else if (tid < 112) {
        int q = tid - 80;               // 0..31: [act 16 | pas 16]
        int dim = (q < 16) ? (2 * q + A) : (2 * (q - 16) + PO);
        float a = anS[ck * 32 + dim];
        float t = anT[ck * 32 + dim];
        float e = __expf(-a);
        B[ANE + q] = e;
        B[ANF + q] = -t * e;
    } else if (tid == 112) {
        float s = 0.f;
        for (int d = 0; d < 32; d++) s += anS[ck * 32 + d];
        B[ASUM] = s;
    }
}

// ---------- one inverse layer: quarter-split hidden, 1 node/thread ----------
DEV_INLINE void layer_compute(const float* __restrict__ sb, int q,
                              ull (&a)[8], ull (&p)[8], float& ld)
{
    // ActNorm inverse (E/F stored in act|pas order)
    const ull* E = (const ull*)(sb + ANE);
    const ull* F = (const ull*)(sb + ANF);
    #pragma unroll
    for (int j = 0; j < 8; j++) {
        a[j] = ffma2(a[j], E[j],     F[j]);
        p[j] = ffma2(p[j], E[8 + j], F[8 + j]);
    }
    ld -= sb[ASUM];

    // 16 outputs as 8 packed pairs
    ull s[8], t[8];
    const ull* b2s = (const ull*)(sb + B2S);
    const ull* b2t = (const ull*)(sb + B2T);
    #pragma unroll
    for (int j = 0; j < 8; j++) {
        s[j] = (q == 0) ? b2s[j] : 0ULL;
        t[j] = (q == 0) ? b2t[j] : 0ULL;
    }

    #pragma unroll 4
    for (int il = 0; il < 16; il++) {
        const int gi = il * 4 + q;                // this thread's hidden unit
        const ulonglong2* r1s = (const ulonglong2*)(sb + W1S + gi * 20);
        const ulonglong2* r1t = (const ulonglong2*)(sb + W1T + gi * 20);
        // 2 partial chains per MLP -> 4 independent FFMA2 chains, depth 4
        ull asA = pack2(sb[B1S + gi], 0.f), asB = 0ULL;
        ull atA = pack2(sb[B1T + gi], 0.f), atB = 0ULL;
        #pragma unroll
        for (int ch = 0; ch < 2; ch++) {
            ulonglong2 ws0 = r1s[ch],     wt0 = r1t[ch];
            ulonglong2 ws1 = r1s[ch + 2], wt1 = r1t[ch + 2];
            asA = ffma2(ws0.x, a[2 * ch],     asA);
            asA = ffma2(ws0.y, a[2 * ch + 1], asA);
            asB = ffma2(ws1.x, a[2 * ch + 4], asB);
            asB = ffma2(ws1.y, a[2 * ch + 5], asB);
            atA = ffma2(wt0.x, a[2 * ch],     atA);
            atA = ffma2(wt0.y, a[2 * ch + 1], atA);
            atB = ffma2(wt1.x, a[2 * ch + 4], atB);
            atB = ffma2(wt1.y, a[2 * ch + 5], atB);
        }
        ull as = add2(asA, asB), at = add2(atA, atB);
        float x0, x1;
        unpack2(as, x0, x1); float hs = fmaxf(x0 + x1, 0.f);
        unpack2(at, x0, x1); float ht = fmaxf(x0 + x1, 0.f);
        ull hsp = pack2(hs, hs), htp = pack2(ht, ht);

        const ulonglong2* r2s = (const ulonglong2*)(sb + W2S + gi * 20);
        const ulonglong2* r2t = (const ulonglong2*)(sb + W2T + gi * 20);
        #pragma unroll
        for (int ch = 0; ch < 4; ch++) {
            ulonglong2 ws = r2s[ch], wt = r2t[ch];
            s[2 * ch]     = ffma2(ws.x, hsp, s[2 * ch]);
            s[2 * ch + 1] = ffma2(ws.y, hsp, s[2 * ch + 1]);
            t[2 * ch]     = ffma2(wt.x, htp, t[2 * ch]);
            t[2 * ch + 1] = ffma2(wt.y, htp, t[2 * ch + 1]);
        }
    }

    // butterfly over the 4 quarter-threads
    #pragma unroll
    for (int j = 0; j < 8; j++) {
        s[j] = add2(s[j], __shfl_xor_sync(0xffffffffu, s[j], 1));
        s[j] = add2(s[j], __shfl_xor_sync(0xffffffffu, s[j], 2));
        t[j] = add2(t[j], __shfl_xor_sync(0xffffffffu, t[j], 1));
        t[j] = add2(t[j], __shfl_xor_sync(0xffffffffu, t[j], 2));
    }

    // passive update + logdet (redundant across quarters, consistent)
    #pragma unroll
    for (int j = 0; j < 8; j++) {
        float sa, sbv;
        unpack2(s[j], sa, sbv);
        ld -= (sa + sbv);
        ull e2 = pack2(__expf(-sa), __expf(-sbv));
        p[j] = ffma2(p[j], e2, neg2(mul2(t[j], e2)));
    }
}

__global__ void __launch_bounds__(128, 3)
flow_kernel(const float* __restrict__ nodes,
            const float* __restrict__ loc, const float* __restrict__ lsc)
{
    __shared__ __align__(16) float sbuf[2][BLOB];
    const int tid  = threadIdx.x;
    const int q    = tid & 3;            // quarter of hidden units
    const int slot = tid >> 2;           // 0..31
    const int c    = blockIdx.y;
    const int node = blockIdx.x * 32 + slot;

    // z packed by parity: ze[j]=(dims 4j,4j+2), zo[j]=(4j+1,4j+3)
    ull ze[8], zo[8];
    {
        const float4* np = (const float4*)(nodes + (size_t)node * 32);
        #pragma unroll
        for (int j = 0; j < 8; j++) {
            float4 v = np[j];
            ze[j] = pack2(v.x, v.z); zo[j] = pack2(v.y, v.w);
        }
    }
    float ld = 0.f;

    const float* gb = g_blob + (size_t)(c * 64) * BLOB;

    stage(sbuf[0], gb + (size_t)63 * BLOB, tid);
    wait_stage();
    __syncthreads();

    #pragma unroll 1
    for (int k = 63; k > 0; k -= 2) {
        stage(sbuf[1], gb + (size_t)(k - 1) * BLOB, tid);
        // layer k (odd): active = odd dims
        layer_compute(sbuf[0], q, zo, ze, ld);
        wait_stage();
        __syncthreads();
        if (k >= 3) stage(sbuf[0], gb + (size_t)(k - 2) * BLOB, tid);
        // layer k-1 (even): active = even dims
        layer_compute(sbuf[1], q, ze, zo, ld);
        wait_stage();
        __syncthreads();
    }

    // DiagGaussian log_prob
    float acc = 0.f;
    const float* lp = loc + c * 32;
    const float* sp = lsc + c * 32;
    #pragma unroll
    for (int j = 0; j < 8; j++) {
        float e0, e1, o0, o1;
        unpack2(ze[j], e0, e1); unpack2(zo[j], o0, o1);
        float z4[4] = {e0, o0, e1, o1};
        #pragma unroll
        for (int b = 0; b < 4; b++) {
            int d = 4 * j + b;
            float ls = __ldg(sp + d);
            float u  = (z4[b] - __ldg(lp + d)) * __expf(-ls);
            acc += ls + 0.5f * u * u;
        }
    }
    if (q == 0)
        g_Bm[c * NN + node] = __expf(ld - 29.406037829f - acc);
}

// Fold L1 row-normalizers and softmax-normalized S into one 8x8 matrix.
__global__ void norm_kernel(const float* __restrict__ S_unc)
{
    __shared__ float sh_r[8];
    __shared__ float sh_e[64];
    const int tid = threadIdx.x;
    const int w = tid >> 5, lane = tid & 31;

    float s = 0.f;
    for (int i = lane; i < NN; i += 32) s += g_Bm[w * NN + i];
    #pragma unroll
    for (int o = 16; o; o >>= 1) s += __shfl_xor_sync(0xffffffffu, s, o);
    if (lane == 0) sh_r[w] = fmaxf(s, 1e-12f);
    if (tid < 64) sh_e[tid] = expf(S_unc[tid]);
    __syncthreads();
    if (tid < 64) {
        float tot = 0.f;
        #pragma unroll
        for (int i = 0; i < 64; i++) tot += sh_e[i];
        int c1 = tid >> 3, c2 = tid & 7;
        g_Sn[tid] = sh_e[tid] / (tot * sh_r[c1] * sh_r[c2]);
    }
}

__global__ void __launch_bounds__(256)
out_kernel(float* __restrict__ out)
{
    __shared__ float B1[8][64];
    __shared__ float B2[8][64];
    __shared__ float T2[8][64];
    const int tid = threadIdx.x;
    const int n10 = blockIdx.y * 64;
    const int n20 = blockIdx.x * 64;

    for (int t = tid; t < 512; t += 256) {
        int cc = t >> 6, j = t & 63;
        B1[cc][j] = g_Bm[cc * NN + n10 + j];
        B2[cc][j] = g_Bm[cc * NN + n20 + j];
    }
    __syncthreads();
    if (tid < 64) {
        #pragma unroll
        for (int c1 = 0; c1 < 8; c1++) {
            float a = 0.f;
            #pragma unroll
            for (int c2 = 0; c2 < 8; c2++)
                a = fmaf(g_Sn[c1 * 8 + c2], B2[c2][tid], a);
            T2[c1][tid] = a;
        }
    }
    __syncthreads();

    const int ty = tid >> 4, tx = tid & 15;
    float bv[4][8], tv[8][4];
    #pragma unroll
    for (int cc = 0; cc < 8; cc++) {
        #pragma unroll
        for (int p = 0; p < 4; p++) {
            bv[p][cc] = B1[cc][ty * 4 + p];
            tv[cc][p] = T2[cc][tx * 4 + p];
        }
    }
    #pragma unroll
    for (int p = 0; p < 4; p++) {
        float4 o = {0.f, 0.f, 0.f, 0.f};
        #pragma unroll
        for (int cc = 0; cc < 8; cc++) {
            o.x = fmaf(bv[p][cc], tv[cc][0], o.x);
            o.y = fmaf(bv[p][cc], tv[cc][1], o.y);
            o.z = fmaf(bv[p][cc], tv[cc][2], o.z);
            o.w = fmaf(bv[p][cc], tv[cc][3], o.w);
        }
        *((float4*)(out + (size_t)(n10 + ty * 4 + p) * NN + n20 + tx * 4)) = o;
    }
}

extern "C" void kernel_launch(void* const* d_in, const int* in_sizes, int n_in,
                              void* d_out, int out_size)
{
    const float* nodes = (const float*)d_in[0];
    const float* sW1   = (const float*)d_in[1];
    const float* sb1   = (const float*)d_in[2];
    const float* sW2   = (const float*)d_in[3];
    const float* sb2   = (const float*)d_in[4];
    const float* tW1   = (const float*)d_in[5];
    const float* tb1   = (const float*)d_in[6];
    const float* tW2   = (const float*)d_in[7];
    const float* tb2   = (const float*)d_in[8];
    const float* anS   = (const float*)d_in[9];
    const float* anT   = (const float*)d_in[10];
    const float* loc   = (const float*)d_in[11];
    const float* lsc   = (const float*)d_in[12];
    const float* S_unc = (const float*)d_in[13];
    float* out = (float*)d_out;

    repack_kernel<<<C * K, 128>>>(sW1, sb1, sW2, sb2, tW1, tb1, tW2, tb2, anS, anT);
    dim3 fg(NN / 32, C);                 // 64 x 8 = 512 blocks, 4 thr/node
    flow_kernel<<<fg, 128>>>(nodes, loc, lsc);
    norm_kernel<<<1, 256>>>(S_unc);
    dim3 og(NN / 64, NN / 64);
    out_kernel<<<og, 256>>>(out);
}